// round 16
// baseline (speedup 1.0000x reference)
#include <cuda_runtime.h>
#include <cuda_fp16.h>

// DeformationGrid: trilinear interpolation of a [160,160,160,3] float grid
// at N=4194304 random points in the unit cube.
//
// R15: exact R4 core (1 point/thread, 4 LDG.128 z-pair fp16 gathers — best
// measured at 83.3us gather / 99.1us total) + L2 eviction-priority pinning:
// the grid is written (repack) and read (gather) with L2::evict_last
// cache-hint policies, so the 65.5MB grid wins L2 replacement against the
// 96MB coord/out streams. R13's ncu proved the binder is gather-miss
// latency (~30% of gather sectors fell to DRAM from stream-induced
// eviction), not L1 wavefronts.

#define GRID_R 160
#define NVOX (GRID_R * GRID_R * GRID_R)   // 4,096,000

// 16B z-pair entry: halves [c0z0,c1z0, c2z0,c0z1, c1z1,c2z1, pad]
__device__ uint4 g_pair[NVOX];            // 65.5 MB scratch (.bss — allowed)

__device__ __forceinline__ unsigned h2_to_u32(__half2 h) {
    return *reinterpret_cast<unsigned*>(&h);
}
__device__ __forceinline__ __half2 u32_to_h2(unsigned u) {
    return *reinterpret_cast<__half2*>(&u);
}

// L2 evict_last annotated 16B load (keeps grid lines resident in L2).
__device__ __forceinline__ uint4 ldg_pin(const uint4* p) {
    uint4 r;
    asm("{\n\t"
        ".reg .b64 pol;\n\t"
        "createpolicy.fractional.L2::evict_last.b64 pol, 1.0;\n\t"
        "ld.global.nc.L2::cache_hint.v4.u32 {%0,%1,%2,%3}, [%4], pol;\n\t"
        "}"
        : "=r"(r.x), "=r"(r.y), "=r"(r.z), "=r"(r.w)
        : "l"(p));
    return r;
}

// L2 evict_last annotated 16B store (grid enters L2 already pinned).
__device__ __forceinline__ void stg_pin(uint4* p, uint4 v) {
    asm volatile(
        "{\n\t"
        ".reg .b64 pol;\n\t"
        "createpolicy.fractional.L2::evict_last.b64 pol, 1.0;\n\t"
        "st.global.L2::cache_hint.v4.u32 [%0], {%1,%2,%3,%4}, pol;\n\t"
        "}"
        :: "l"(p), "r"(v.x), "r"(v.y), "r"(v.z), "r"(v.w)
        : "memory");
}

// ---------------------------------------------------------------------------
// Repack: one block per (x,y) row of 160 z-voxels. Coalesced.
// ---------------------------------------------------------------------------
__global__ void __launch_bounds__(160)
repack_kernel(const float* __restrict__ theta)
{
    __shared__ float s[480];
    int row = blockIdx.x;                  // x*160 + y
    int t = threadIdx.x;                   // 0..159
    const float* src = theta + (size_t)row * 480;
    s[t]       = __ldg(src + t);
    s[t + 160] = __ldg(src + t + 160);
    s[t + 320] = __ldg(src + t + 320);
    __syncthreads();

    int z1 = min(t + 1, GRID_R - 1);       // z=159 entry: weight-0 duplicate
    uint4 e;
    e.x = h2_to_u32(__floats2half2_rn(s[3 * t + 0], s[3 * t + 1]));
    e.y = h2_to_u32(__floats2half2_rn(s[3 * t + 2], s[3 * z1 + 0]));
    e.z = h2_to_u32(__floats2half2_rn(s[3 * z1 + 1], s[3 * z1 + 2]));
    e.w = 0u;
    stg_pin(&g_pair[(size_t)row * GRID_R + t], e);
}

// ---------------------------------------------------------------------------
// Gather: one thread per point, 4 pinned LDG.128 gathers, fused lerps.
// ---------------------------------------------------------------------------
__device__ __forceinline__ float flerp(float a, float b, float t) {
    return fmaf(t, b - a, a);
}

__device__ __forceinline__ void zlerp_entry(uint4 e, float fz,
                                            float& r0, float& r1, float& r2)
{
    float2 p0 = __half22float2(u32_to_h2(e.x));   // (c0z0, c1z0)
    float2 p1 = __half22float2(u32_to_h2(e.y));   // (c2z0, c0z1)
    float2 p2 = __half22float2(u32_to_h2(e.z));   // (c1z1, c2z1)
    r0 = flerp(p0.x, p1.y, fz);
    r1 = flerp(p0.y, p2.x, fz);
    r2 = flerp(p1.x, p2.y, fz);
}

__global__ void __launch_bounds__(256)
trilerp_kernel(const float* __restrict__ coords,
               float* __restrict__ out,
               int n)
{
    int i = blockIdx.x * blockDim.x + threadIdx.x;
    if (i >= n) return;

    float cx = coords[3 * i + 0];
    float cy = coords[3 * i + 1];
    float cz = coords[3 * i + 2];

    const float scale = (float)(GRID_R - 1);   // 159
    float px = cx * scale, py = cy * scale, pz = cz * scale;

    float fx0 = floorf(px), fy0 = floorf(py), fz0 = floorf(pz);
    float fx = px - fx0, fy = py - fy0, fz = pz - fz0;

    int ix = (int)fx0, iy = (int)fy0, iz = (int)fz0;
    // Safety clamps. In-range coords: no-ops. Upper boundary: the +1 corner
    // has weight 0, so replicate-clamp matches cval=0 semantics.
    ix = min(max(ix, 0), GRID_R - 1);
    iy = min(max(iy, 0), GRID_R - 1);
    iz = min(max(iz, 0), GRID_R - 1);
    int ix1 = min(ix + 1, GRID_R - 1);
    int iy1 = min(iy + 1, GRID_R - 1);

    const int SX = GRID_R * GRID_R;
    const int SY = GRID_R;

    int b00 = ix  * SX + iy  * SY + iz;
    int b01 = ix  * SX + iy1 * SY + iz;
    int b10 = ix1 * SX + iy  * SY + iz;
    int b11 = ix1 * SX + iy1 * SY + iz;

    // 4 pinned gathers, each returns both z-corners for one (x,y) combo.
    uint4 e00 = ldg_pin(g_pair + b00);
    uint4 e01 = ldg_pin(g_pair + b01);
    uint4 e10 = ldg_pin(g_pair + b10);
    uint4 e11 = ldg_pin(g_pair + b11);

    float c00x, c00y, c00z, c01x, c01y, c01z;
    float c10x, c10y, c10z, c11x, c11y, c11z;
    zlerp_entry(e00, fz, c00x, c00y, c00z);
    zlerp_entry(e01, fz, c01x, c01y, c01z);
    zlerp_entry(e10, fz, c10x, c10y, c10z);
    zlerp_entry(e11, fz, c11x, c11y, c11z);

    // lerp along y
    float c0x = flerp(c00x, c01x, fy), c0y = flerp(c00y, c01y, fy), c0z = flerp(c00z, c01z, fy);
    float c1x = flerp(c10x, c11x, fy), c1y = flerp(c10y, c11y, fy), c1z = flerp(c10z, c11z, fy);
    // lerp along x
    out[3 * i + 0] = flerp(c0x, c1x, fx);
    out[3 * i + 1] = flerp(c0y, c1y, fx);
    out[3 * i + 2] = flerp(c0z, c1z, fx);
}

extern "C" void kernel_launch(void* const* d_in, const int* in_sizes, int n_in,
                              void* d_out, int out_size) {
    const float* coords = (const float*)d_in[0];   // [N,3]
    const float* theta  = (const float*)d_in[1];   // [160,160,160,3]
    float* out = (float*)d_out;                    // [N,3]
    int n = in_sizes[0] / 3;

    repack_kernel<<<GRID_R * GRID_R, GRID_R>>>(theta);

    int threads = 256;
    int blocks = (n + threads - 1) / threads;
    trilerp_kernel<<<blocks, threads>>>(coords, out, n);
}

// round 17
// speedup vs baseline: 1.0271x; 1.0271x over previous
#include <cuda_runtime.h>
#include <cuda_fp16.h>

// DeformationGrid: trilinear interpolation of a [160,160,160,3] float grid
// at N=4194304 random points in the unit cube.
//
// R16: wavefront-minimal variant. Model (fits all 6 measured rounds):
// time = total L1 wavefronts / (148 SM x 1 wf/cyc). R4 spends 128 wf/warp
// on gathers (layout floor) + 18 wf on scalar stride-12B coord/out streams.
// Here: 2 points per thread so streams are 3x LDG.64 + 3x STG.64 = 6 wf
// (-12 wf/warp), while gathers are issued in two sequential 4-load phases
// so the front-batched load count (MLP_p1 ~ 7) matches R4 — avoiding the
// cross-CTA L1tex-queue spread that sank the R5 8-batched variant.

#define GRID_R 160
#define NVOX (GRID_R * GRID_R * GRID_R)   // 4,096,000

// 16B z-pair entry: halves [c0z0,c1z0, c2z0,c0z1, c1z1,c2z1, pad]
__device__ uint4 g_pair[NVOX];            // 65.5 MB scratch (.bss — allowed)

__device__ __forceinline__ unsigned h2_to_u32(__half2 h) {
    return *reinterpret_cast<unsigned*>(&h);
}
__device__ __forceinline__ __half2 u32_to_h2(unsigned u) {
    return *reinterpret_cast<__half2*>(&u);
}

// ---------------------------------------------------------------------------
// Repack: one block per (x,y) row of 160 z-voxels. Coalesced, HBM-bound.
// ---------------------------------------------------------------------------
__global__ void __launch_bounds__(160)
repack_kernel(const float* __restrict__ theta)
{
    __shared__ float s[480];
    int row = blockIdx.x;                  // x*160 + y
    int t = threadIdx.x;                   // 0..159
    const float* src = theta + (size_t)row * 480;
    s[t]       = __ldg(src + t);
    s[t + 160] = __ldg(src + t + 160);
    s[t + 320] = __ldg(src + t + 320);
    __syncthreads();

    int z1 = min(t + 1, GRID_R - 1);       // z=159 entry: weight-0 duplicate
    uint4 e;
    e.x = h2_to_u32(__floats2half2_rn(s[3 * t + 0], s[3 * t + 1]));
    e.y = h2_to_u32(__floats2half2_rn(s[3 * t + 2], s[3 * z1 + 0]));
    e.z = h2_to_u32(__floats2half2_rn(s[3 * z1 + 1], s[3 * z1 + 2]));
    e.w = 0u;
    g_pair[(size_t)row * GRID_R + t] = e;
}

// ---------------------------------------------------------------------------
// Gather: 2 points per thread; vectorized float2 streams; two sequential
// 4-gather phases (keeps MLP_p1 at the proven R4 level).
// ---------------------------------------------------------------------------
__device__ __forceinline__ float flerp(float a, float b, float t) {
    return fmaf(t, b - a, a);
}

__device__ __forceinline__ void zlerp_entry(uint4 e, float fz,
                                            float& r0, float& r1, float& r2)
{
    float2 p0 = __half22float2(u32_to_h2(e.x));   // (c0z0, c1z0)
    float2 p1 = __half22float2(u32_to_h2(e.y));   // (c2z0, c0z1)
    float2 p2 = __half22float2(u32_to_h2(e.z));   // (c1z1, c2z1)
    r0 = flerp(p0.x, p1.y, fz);
    r1 = flerp(p0.y, p2.x, fz);
    r2 = flerp(p1.x, p2.y, fz);
}

// Compute the 4 entry offsets + fracs for one point.
__device__ __forceinline__ void point_addrs(float cx, float cy, float cz,
                                            int& b00, int& b01, int& b10, int& b11,
                                            float& fx, float& fy, float& fz)
{
    const float scale = (float)(GRID_R - 1);
    float px = cx * scale, py = cy * scale, pz = cz * scale;
    float fx0 = floorf(px), fy0 = floorf(py), fz0 = floorf(pz);
    fx = px - fx0; fy = py - fy0; fz = pz - fz0;
    int ix = (int)fx0, iy = (int)fy0, iz = (int)fz0;
    // Safety clamps; +1 corners at the boundary have weight 0 (cval=0 ok).
    ix = min(max(ix, 0), GRID_R - 1);
    iy = min(max(iy, 0), GRID_R - 1);
    iz = min(max(iz, 0), GRID_R - 1);
    int ix1 = min(ix + 1, GRID_R - 1);
    int iy1 = min(iy + 1, GRID_R - 1);
    const int SX = GRID_R * GRID_R, SY = GRID_R;
    b00 = ix  * SX + iy  * SY + iz;
    b01 = ix  * SX + iy1 * SY + iz;
    b10 = ix1 * SX + iy  * SY + iz;
    b11 = ix1 * SX + iy1 * SY + iz;
}

// Gather 4 entries and finish one point.
__device__ __forceinline__ void do_point(int b00, int b01, int b10, int b11,
                                         float fx, float fy, float fz,
                                         float& rx, float& ry, float& rz)
{
    uint4 e00 = __ldg(g_pair + b00);
    uint4 e01 = __ldg(g_pair + b01);
    uint4 e10 = __ldg(g_pair + b10);
    uint4 e11 = __ldg(g_pair + b11);

    float c00x, c00y, c00z, c01x, c01y, c01z;
    float c10x, c10y, c10z, c11x, c11y, c11z;
    zlerp_entry(e00, fz, c00x, c00y, c00z);
    zlerp_entry(e01, fz, c01x, c01y, c01z);
    zlerp_entry(e10, fz, c10x, c10y, c10z);
    zlerp_entry(e11, fz, c11x, c11y, c11z);

    float c0x = flerp(c00x, c01x, fy), c0y = flerp(c00y, c01y, fy), c0z = flerp(c00z, c01z, fy);
    float c1x = flerp(c10x, c11x, fy), c1y = flerp(c10y, c11y, fy), c1z = flerp(c10z, c11z, fy);
    rx = flerp(c0x, c1x, fx);
    ry = flerp(c0y, c1y, fx);
    rz = flerp(c0z, c1z, fx);
}

__global__ void __launch_bounds__(256)
trilerp_kernel(const float* __restrict__ coords,
               float* __restrict__ out,
               int n)
{
    int t = blockIdx.x * blockDim.x + threadIdx.x;
    int p = 2 * t;
    if (p >= n) return;

    if (p + 1 < n) {
        // Vectorized coord load: floats [6t, 6t+6) as 3x LDG.64.
        const float2* c2 = (const float2*)coords;
        float2 A = __ldg(c2 + 3 * t + 0);   // (x0, y0)
        float2 B = __ldg(c2 + 3 * t + 1);   // (z0, x1)
        float2 C = __ldg(c2 + 3 * t + 2);   // (y1, z1)

        int a00, a01, a10, a11, b00, b01, b10, b11;
        float fx0, fy0, fz0, fx1, fy1, fz1;
        point_addrs(A.x, A.y, B.x, a00, a01, a10, a11, fx0, fy0, fz0);
        point_addrs(B.y, C.x, C.y, b00, b01, b10, b11, fx1, fy1, fz1);

        // Phase 1: point 0 gathers + finish (4 loads in flight).
        float r0x, r0y, r0z;
        do_point(a00, a01, a10, a11, fx0, fy0, fz0, r0x, r0y, r0z);

        // Phase 2: point 1 gathers + finish.
        float r1x, r1y, r1z;
        do_point(b00, b01, b10, b11, fx1, fy1, fz1, r1x, r1y, r1z);

        // Vectorized stores: 3x STG.64.
        float2* o2 = (float2*)out;
        o2[3 * t + 0] = make_float2(r0x, r0y);
        o2[3 * t + 1] = make_float2(r0z, r1x);
        o2[3 * t + 2] = make_float2(r1y, r1z);
    } else {
        // Tail: single point, scalar path.
        float cx = coords[3 * p + 0];
        float cy = coords[3 * p + 1];
        float cz = coords[3 * p + 2];
        int b00, b01, b10, b11;
        float fx, fy, fz;
        point_addrs(cx, cy, cz, b00, b01, b10, b11, fx, fy, fz);
        float rx, ry, rz;
        do_point(b00, b01, b10, b11, fx, fy, fz, rx, ry, rz);
        out[3 * p + 0] = rx;
        out[3 * p + 1] = ry;
        out[3 * p + 2] = rz;
    }
}

extern "C" void kernel_launch(void* const* d_in, const int* in_sizes, int n_in,
                              void* d_out, int out_size) {
    const float* coords = (const float*)d_in[0];   // [N,3]
    const float* theta  = (const float*)d_in[1];   // [160,160,160,3]
    float* out = (float*)d_out;                    // [N,3]
    int n = in_sizes[0] / 3;

    repack_kernel<<<GRID_R * GRID_R, GRID_R>>>(theta);

    int threads = 256;
    int pairs = (n + 1) / 2;
    int blocks = (pairs + threads - 1) / threads;
    trilerp_kernel<<<blocks, threads>>>(coords, out, n);
}